// round 6
// baseline (speedup 1.0000x reference)
#include <cuda_runtime.h>
#include <cuda_fp16.h>
#include <math.h>
#include <stdint.h>

// ---------------- problem constants ----------------
static constexpr int NUSERS = 100000;
static constexpr int NITEMS = 50000;
static constexpr int NNODE  = 150000;       // NUSERS + NITEMS
static constexpr int NEDGE  = 1200000;      // 2 * 600000
static constexpr int DIM    = 64;
static constexpr int SCANB  = (NNODE + 1023) / 1024;   // 147 scan blocks
static constexpr int VECB   = (NNODE * 16 + 255) / 256; // init blocks (16 lanes/node)
static constexpr int EDGEB  = (NEDGE + 255) / 256;      // mlp blocks

// ---------------- device scratch (static; no runtime alloc) ----------------
// Invariant: g_wdeg/g_cnt are ZERO at kernel_launch entry (static init covers the
// first call; final_kernel re-zeros them at the end of every call).
__device__ float  g_edge_w[NEDGE];
__device__ int2   g_edge[NEDGE];            // {src, __float_as_int(edge_w * dinv[src])}
__device__ float  g_wdeg[NNODE];
__device__ float  g_dinv[NNODE];
__device__ int    g_cnt[NNODE];
__device__ int    g_rowptr[NNODE + 1];
__device__ int    g_cursor[NNODE];
__device__ int    g_aggval[SCANB];
__device__ int    g_aggflag[SCANB];
__device__ __half g_x0[(size_t)NNODE * DIM];
__device__ __half g_x1[(size_t)NNODE * DIM];
__device__ __half g_x2[(size_t)NNODE * DIM];
__device__ __half g_x3[(size_t)NNODE * DIM];
__device__ __half* const g_xptr[4] = {g_x0, g_x1, g_x2, g_x3};

// ---------------- fused init + mlp ----------------
// blocks [0, VECB): node init (x0 = l2norm(...)), also zero scan flags
// blocks [VECB, VECB+EDGEB): edge MLP + weighted-degree/count histogram
__global__ void __launch_bounds__(256) initmlp_kernel(
        const float* __restrict__ uemb,  const float* __restrict__ audio,
        const float* __restrict__ art,   const float* __restrict__ alb,
        const int*   __restrict__ aid,   const int*   __restrict__ bid,
        const float* __restrict__ ef,
        const float* __restrict__ w1,    const float* __restrict__ b1,
        const float* __restrict__ w2,    const float* __restrict__ b2,
        const int*   __restrict__ eidx) {
    int t = threadIdx.x;
    if (blockIdx.x < VECB) {
        int g = blockIdx.x * 256 + t;
        if (g < SCANB) g_aggflag[g] = 0;     // reset lookback flags for scan

        int node = g >> 4;
        int sub  = g & 15;
        if (node >= NNODE) return;

        float4 v;
        if (node < NUSERS) {
            v = __ldg(reinterpret_cast<const float4*>(uemb) + (size_t)node * 16 + sub);
        } else {
            int i = node - NUSERS;
            int a = __ldg(&aid[i]);
            int b = __ldg(&bid[i]);
            float4 pa = __ldg(reinterpret_cast<const float4*>(audio) + (size_t)i * 16 + sub);
            float4 pr = __ldg(reinterpret_cast<const float4*>(art)   + (size_t)a * 16 + sub);
            float4 pl = __ldg(reinterpret_cast<const float4*>(alb)   + (size_t)b * 16 + sub);
            v.x = pa.x * 0.3f + (pr.x + pl.x) * 0.44f;
            v.y = pa.y * 0.3f + (pr.y + pl.y) * 0.44f;
            v.z = pa.z * 0.3f + (pr.z + pl.z) * 0.44f;
            v.w = pa.w * 0.3f + (pr.w + pl.w) * 0.44f;
        }
        float ss = v.x * v.x + v.y * v.y + v.z * v.z + v.w * v.w;
        #pragma unroll
        for (int o = 8; o > 0; o >>= 1) ss += __shfl_xor_sync(0xffffffffu, ss, o);
        float inv = 1.f / fmaxf(sqrtf(ss), 1e-12f);

        __half2 h0 = __floats2half2_rn(v.x * inv, v.y * inv);
        __half2 h1 = __floats2half2_rn(v.z * inv, v.w * inv);
        uint2 hv;
        hv.x = *reinterpret_cast<unsigned int*>(&h0);
        hv.y = *reinterpret_cast<unsigned int*>(&h1);
        reinterpret_cast<uint2*>(g_x0)[(size_t)node * 16 + sub] = hv;
    } else {
        __shared__ float sW1[8 * 32];
        __shared__ float sB1[32];
        __shared__ float sW2[32];
        __shared__ float sB2;
        if (t < 256) sW1[t] = w1[t];
        if (t < 32)  { sB1[t] = b1[t]; sW2[t] = w2[t]; }
        if (t == 0)  sB2 = b2[0];
        __syncthreads();

        int e = (blockIdx.x - VECB) * 256 + t;
        if (e >= NEDGE) return;

        const float4* fp = reinterpret_cast<const float4*>(ef + (size_t)e * 8);
        float4 fa = fp[0];
        float4 fb = fp[1];
        float f[8] = {fa.x, fa.y, fa.z, fa.w, fb.x, fb.y, fb.z, fb.w};

        float out = sB2;
        #pragma unroll
        for (int j = 0; j < 32; j++) {
            float h = sB1[j];
            #pragma unroll
            for (int i = 0; i < 8; i++) h = fmaf(f[i], sW1[i * 32 + j], h);
            h = fmaxf(h, 0.f);
            out = fmaf(h, sW2[j], out);
        }
        float w = 1.f / (1.f + expf(-out));

        g_edge_w[e] = w;
        int c = eidx[NEDGE + e];
        atomicAdd(&g_wdeg[c], w);
        atomicAdd(&g_cnt[c], 1);
    }
}

// ---------------- single-launch scan (decoupled lookback) ----------------
// 147 blocks of 1024 — all resident in one wave (147 < 148 SMs), so spinning
// on predecessor aggregates cannot deadlock.
__global__ void __launch_bounds__(1024) scan_kernel() {
    __shared__ int sh[1024];
    __shared__ int sh2[1024];
    int t = threadIdx.x;
    int b = blockIdx.x;
    int n = b * 1024 + t;
    int c = (n < NNODE) ? g_cnt[n] : 0;

    // local inclusive scan
    sh[t] = c;
    __syncthreads();
    for (int off = 1; off < 1024; off <<= 1) {
        int v = (t >= off) ? sh[t - off] : 0;
        __syncthreads();
        sh[t] += v;
        __syncthreads();
    }
    int incl = sh[t];

    // publish block aggregate
    if (t == 1023) {
        *(volatile int*)&g_aggval[b] = incl;
        __threadfence();
        *(volatile int*)&g_aggflag[b] = 1;
    }

    // lookback: thread j (< b) fetches aggregate of block j
    int part = 0;
    if (t < b) {
        while (*(volatile int*)&g_aggflag[t] == 0) { }
        part = *(volatile int*)&g_aggval[t];
    }
    sh2[t] = part;
    __syncthreads();
    for (int off = 512; off > 0; off >>= 1) {
        if (t < off) sh2[t] += sh2[t + off];
        __syncthreads();
    }
    int blockOff = sh2[0];

    if (n < NNODE) {
        int p = blockOff + incl - c;    // global exclusive prefix
        g_rowptr[n] = p;
        g_cursor[n] = p;
        float dg = g_wdeg[n];
        g_dinv[n] = (dg > 0.f) ? rsqrtf(dg) : 0.f;
    }
    if (b == 0 && t == 0) g_rowptr[NNODE] = NEDGE;
}

// bucket edges by destination; store {src, edge_w * dinv[src]}; 2 edges/thread
__global__ void __launch_bounds__(256) scatter_kernel(const int* __restrict__ eidx) {
    int e = (blockIdx.x * blockDim.x + threadIdx.x) * 2;
    if (e >= NEDGE) return;
    int2   r2 = __ldg(reinterpret_cast<const int2*>(eidx + e));
    int2   c2 = __ldg(reinterpret_cast<const int2*>(eidx + NEDGE + e));
    float2 w2 = __ldg(reinterpret_cast<const float2*>(g_edge_w + e));

    float wa = w2.x * __ldg(&g_dinv[r2.x]);
    int pa = atomicAdd(&g_cursor[c2.x], 1);
    g_edge[pa] = make_int2(r2.x, __float_as_int(wa));

    float wb = w2.y * __ldg(&g_dinv[r2.y]);
    int pb = atomicAdd(&g_cursor[c2.y], 1);
    g_edge[pb] = make_int2(r2.y, __float_as_int(wb));
}

// one propagation layer: x[l+1][n] = dinv[n] * sum_e w'_e * x[l][src_e]
// warp = 1 node, 8 edges/iter (2 groups of 4), cross-iteration meta prefetch.
__global__ void __launch_bounds__(256) gather_kernel(int layer) {
    const uint4* __restrict__ xin  = reinterpret_cast<const uint4*>(g_xptr[layer]);
    uint4*       __restrict__ xout = reinterpret_cast<uint4*>(g_xptr[layer + 1]);

    int warp = (blockIdx.x * blockDim.x + threadIdx.x) >> 5;
    int lane = threadIdx.x & 31;
    if (warp >= NNODE) return;
    int slot = lane >> 3;     // 0..3 : edge within group of 4
    int sub  = lane & 7;      // 0..7 : 16B chunk of the 128B row

    int beg = g_rowptr[warp];
    int end = g_rowptr[warp + 1];

    float a[8] = {0.f, 0.f, 0.f, 0.f, 0.f, 0.f, 0.f, 0.f};
    int2 mA = (beg + slot     < end) ? __ldg(&g_edge[beg + slot])     : make_int2(0, 0);
    int2 mB = (beg + 4 + slot < end) ? __ldg(&g_edge[beg + 4 + slot]) : make_int2(0, 0);

    for (int e = beg; e < end; e += 8) {
        int2 c0 = mA, c1 = mB;
        int en = e + 8;
        if (en < end) {
            mA = (en + slot     < end) ? __ldg(&g_edge[en + slot])     : make_int2(0, 0);
            mB = (en + 4 + slot < end) ? __ldg(&g_edge[en + 4 + slot]) : make_int2(0, 0);
        }
        float w0 = __int_as_float(c0.y);
        float w1 = __int_as_float(c1.y);
        uint4 v0 = __ldg(xin + (size_t)c0.x * 8 + sub);
        uint4 v1 = __ldg(xin + (size_t)c1.x * 8 + sub);

        float2 f0 = __half22float2(*reinterpret_cast<__half2*>(&v0.x));
        float2 f1 = __half22float2(*reinterpret_cast<__half2*>(&v0.y));
        float2 f2 = __half22float2(*reinterpret_cast<__half2*>(&v0.z));
        float2 f3 = __half22float2(*reinterpret_cast<__half2*>(&v0.w));
        a[0] = fmaf(w0, f0.x, a[0]); a[1] = fmaf(w0, f0.y, a[1]);
        a[2] = fmaf(w0, f1.x, a[2]); a[3] = fmaf(w0, f1.y, a[3]);
        a[4] = fmaf(w0, f2.x, a[4]); a[5] = fmaf(w0, f2.y, a[5]);
        a[6] = fmaf(w0, f3.x, a[6]); a[7] = fmaf(w0, f3.y, a[7]);

        float2 g0 = __half22float2(*reinterpret_cast<__half2*>(&v1.x));
        float2 g1 = __half22float2(*reinterpret_cast<__half2*>(&v1.y));
        float2 g2 = __half22float2(*reinterpret_cast<__half2*>(&v1.z));
        float2 g3 = __half22float2(*reinterpret_cast<__half2*>(&v1.w));
        a[0] = fmaf(w1, g0.x, a[0]); a[1] = fmaf(w1, g0.y, a[1]);
        a[2] = fmaf(w1, g1.x, a[2]); a[3] = fmaf(w1, g1.y, a[3]);
        a[4] = fmaf(w1, g2.x, a[4]); a[5] = fmaf(w1, g2.y, a[5]);
        a[6] = fmaf(w1, g3.x, a[6]); a[7] = fmaf(w1, g3.y, a[7]);
    }
    #pragma unroll
    for (int i = 0; i < 8; i++) {
        a[i] += __shfl_xor_sync(0xffffffffu, a[i], 8);
        a[i] += __shfl_xor_sync(0xffffffffu, a[i], 16);
    }

    if (slot == 0) {
        float dv = __ldg(&g_dinv[warp]);
        __half2 h0 = __floats2half2_rn(a[0] * dv, a[1] * dv);
        __half2 h1 = __floats2half2_rn(a[2] * dv, a[3] * dv);
        __half2 h2 = __floats2half2_rn(a[4] * dv, a[5] * dv);
        __half2 h3 = __floats2half2_rn(a[6] * dv, a[7] * dv);
        uint4 o;
        o.x = *reinterpret_cast<unsigned int*>(&h0);
        o.y = *reinterpret_cast<unsigned int*>(&h1);
        o.z = *reinterpret_cast<unsigned int*>(&h2);
        o.w = *reinterpret_cast<unsigned int*>(&h3);
        xout[(size_t)warp * 8 + sub] = o;
    }
}

// out = l2norm((x0+x1+x2+x3) / 4); trailing align_loss = 0.
// Also re-zeros g_wdeg/g_cnt for the next kernel_launch call.
__global__ void __launch_bounds__(256) final_kernel(float* __restrict__ out) {
    int t = blockIdx.x * blockDim.x + threadIdx.x;
    if (t < NNODE) { g_wdeg[t] = 0.f; g_cnt[t] = 0; }

    int node = t >> 3;
    int sub  = t & 7;
    if (node >= NNODE) return;

    size_t o = (size_t)node * 8 + sub;
    float a[8] = {0.f, 0.f, 0.f, 0.f, 0.f, 0.f, 0.f, 0.f};
    #pragma unroll
    for (int l = 0; l < 4; l++) {
        uint4 v = reinterpret_cast<const uint4*>(g_xptr[l])[o];
        float2 f0 = __half22float2(*reinterpret_cast<__half2*>(&v.x));
        float2 f1 = __half22float2(*reinterpret_cast<__half2*>(&v.y));
        float2 f2 = __half22float2(*reinterpret_cast<__half2*>(&v.z));
        float2 f3 = __half22float2(*reinterpret_cast<__half2*>(&v.w));
        a[0] += f0.x; a[1] += f0.y; a[2] += f1.x; a[3] += f1.y;
        a[4] += f2.x; a[5] += f2.y; a[6] += f3.x; a[7] += f3.y;
    }
    float ss = 0.f;
    #pragma unroll
    for (int i = 0; i < 8; i++) { a[i] *= 0.25f; ss = fmaf(a[i], a[i], ss); }
    #pragma unroll
    for (int oo = 4; oo > 0; oo >>= 1) ss += __shfl_xor_sync(0xffffffffu, ss, oo);
    float inv = 1.f / fmaxf(sqrtf(ss), 1e-12f);

    float4* op = reinterpret_cast<float4*>(out);
    op[(size_t)node * 16 + 2 * sub]     = make_float4(a[0] * inv, a[1] * inv, a[2] * inv, a[3] * inv);
    op[(size_t)node * 16 + 2 * sub + 1] = make_float4(a[4] * inv, a[5] * inv, a[6] * inv, a[7] * inv);

    if (blockIdx.x == 0 && threadIdx.x == 0) out[(size_t)NNODE * DIM] = 0.f;
}

// ---------------- launcher ----------------
extern "C" void kernel_launch(void* const* d_in, const int* in_sizes, int n_in,
                              void* d_out, int out_size) {
    const float* uemb  = (const float*)d_in[0];
    const float* audio = (const float*)d_in[1];
    const float* art   = (const float*)d_in[2];
    const float* alb   = (const float*)d_in[3];
    const float* w1    = (const float*)d_in[4];
    const float* b1    = (const float*)d_in[5];
    const float* w2    = (const float*)d_in[6];
    const float* b2    = (const float*)d_in[7];
    const float* ef    = (const float*)d_in[8];
    const int*   eidx  = (const int*)  d_in[9];
    const int*   aid   = (const int*)  d_in[10];
    const int*   bid   = (const int*)  d_in[11];
    float* out = (float*)d_out;

    const int edge2Blocks = (NEDGE / 2 + 255) / 256;
    const int warpBlocks  = (NNODE * 32 + 255) / 256;   // one warp per node
    const int octBlocks   = (NNODE * 8  + 255) / 256;   // 8 lanes per node

    initmlp_kernel<<<VECB + EDGEB, 256>>>(uemb, audio, art, alb, aid, bid,
                                          ef, w1, b1, w2, b2, eidx);
    scan_kernel   <<<SCANB, 1024>>>();
    scatter_kernel<<<edge2Blocks, 256>>>(eidx);
    gather_kernel <<<warpBlocks, 256>>>(0);   // x0 -> x1   (ncu launch index 3)
    gather_kernel <<<warpBlocks, 256>>>(1);   // x1 -> x2
    gather_kernel <<<warpBlocks, 256>>>(2);   // x2 -> x3
    final_kernel  <<<octBlocks, 256>>>(out);
}

// round 7
// speedup vs baseline: 1.1143x; 1.1143x over previous
#include <cuda_runtime.h>
#include <cuda_fp16.h>
#include <math.h>
#include <stdint.h>

// ---------------- problem constants ----------------
static constexpr int NUSERS = 100000;
static constexpr int NITEMS = 50000;
static constexpr int NNODE  = 150000;       // NUSERS + NITEMS
static constexpr int NEDGE  = 1200000;      // 2 * 600000
static constexpr int DIM    = 64;
static constexpr int SCANB  = (NNODE + 1023) / 1024;   // 147 scan blocks
static constexpr int VECB   = (NNODE * 16 + 255) / 256; // init blocks (16 lanes/node)
static constexpr int EDGEB  = (NEDGE + 255) / 256;      // mlp blocks

// ---------------- device scratch (static; no runtime alloc) ----------------
// Invariant: g_wdeg/g_cnt are ZERO at kernel_launch entry (static init covers the
// first call; the fused gather+final kernel re-zeros them every call).
__device__ float  g_edge_w[NEDGE];
__device__ int2   g_edge[NEDGE];            // {src, __float_as_int(edge_w * dinv[src])}
__device__ float  g_wdeg[NNODE];
__device__ float  g_dinv[NNODE];
__device__ int    g_cnt[NNODE];
__device__ int    g_rowptr[NNODE + 1];
__device__ int    g_cursor[NNODE];
__device__ int    g_aggval[SCANB];
__device__ int    g_aggflag[SCANB];
__device__ __half g_x0[(size_t)NNODE * DIM];
__device__ __half g_x1[(size_t)NNODE * DIM];
__device__ __half g_x2[(size_t)NNODE * DIM];
__device__ __half* const g_xptr[3] = {g_x0, g_x1, g_x2};

// ---------------- fused init + mlp ----------------
__global__ void __launch_bounds__(256) initmlp_kernel(
        const float* __restrict__ uemb,  const float* __restrict__ audio,
        const float* __restrict__ art,   const float* __restrict__ alb,
        const int*   __restrict__ aid,   const int*   __restrict__ bid,
        const float* __restrict__ ef,
        const float* __restrict__ w1,    const float* __restrict__ b1,
        const float* __restrict__ w2,    const float* __restrict__ b2,
        const int*   __restrict__ eidx) {
    int t = threadIdx.x;
    if (blockIdx.x < VECB) {
        int g = blockIdx.x * 256 + t;
        if (g < SCANB) g_aggflag[g] = 0;     // reset lookback flags for scan

        int node = g >> 4;
        int sub  = g & 15;
        if (node >= NNODE) return;

        float4 v;
        if (node < NUSERS) {
            v = __ldg(reinterpret_cast<const float4*>(uemb) + (size_t)node * 16 + sub);
        } else {
            int i = node - NUSERS;
            int a = __ldg(&aid[i]);
            int b = __ldg(&bid[i]);
            float4 pa = __ldg(reinterpret_cast<const float4*>(audio) + (size_t)i * 16 + sub);
            float4 pr = __ldg(reinterpret_cast<const float4*>(art)   + (size_t)a * 16 + sub);
            float4 pl = __ldg(reinterpret_cast<const float4*>(alb)   + (size_t)b * 16 + sub);
            v.x = pa.x * 0.3f + (pr.x + pl.x) * 0.44f;
            v.y = pa.y * 0.3f + (pr.y + pl.y) * 0.44f;
            v.z = pa.z * 0.3f + (pr.z + pl.z) * 0.44f;
            v.w = pa.w * 0.3f + (pr.w + pl.w) * 0.44f;
        }
        float ss = v.x * v.x + v.y * v.y + v.z * v.z + v.w * v.w;
        #pragma unroll
        for (int o = 8; o > 0; o >>= 1) ss += __shfl_xor_sync(0xffffffffu, ss, o);
        float inv = 1.f / fmaxf(sqrtf(ss), 1e-12f);

        __half2 h0 = __floats2half2_rn(v.x * inv, v.y * inv);
        __half2 h1 = __floats2half2_rn(v.z * inv, v.w * inv);
        uint2 hv;
        hv.x = *reinterpret_cast<unsigned int*>(&h0);
        hv.y = *reinterpret_cast<unsigned int*>(&h1);
        reinterpret_cast<uint2*>(g_x0)[(size_t)node * 16 + sub] = hv;
    } else {
        __shared__ float sW1[8 * 32];
        __shared__ float sB1[32];
        __shared__ float sW2[32];
        __shared__ float sB2;
        if (t < 256) sW1[t] = w1[t];
        if (t < 32)  { sB1[t] = b1[t]; sW2[t] = w2[t]; }
        if (t == 0)  sB2 = b2[0];
        __syncthreads();

        int e = (blockIdx.x - VECB) * 256 + t;
        if (e >= NEDGE) return;

        const float4* fp = reinterpret_cast<const float4*>(ef + (size_t)e * 8);
        float4 fa = fp[0];
        float4 fb = fp[1];
        float f[8] = {fa.x, fa.y, fa.z, fa.w, fb.x, fb.y, fb.z, fb.w};

        float out = sB2;
        #pragma unroll
        for (int j = 0; j < 32; j++) {
            float h = sB1[j];
            #pragma unroll
            for (int i = 0; i < 8; i++) h = fmaf(f[i], sW1[i * 32 + j], h);
            h = fmaxf(h, 0.f);
            out = fmaf(h, sW2[j], out);
        }
        float w = 1.f / (1.f + expf(-out));

        g_edge_w[e] = w;
        int c = eidx[NEDGE + e];
        atomicAdd(&g_wdeg[c], w);
        atomicAdd(&g_cnt[c], 1);
    }
}

// ---------------- single-launch scan (decoupled lookback) ----------------
__global__ void __launch_bounds__(1024) scan_kernel() {
    __shared__ int sh[1024];
    __shared__ int sh2[1024];
    int t = threadIdx.x;
    int b = blockIdx.x;
    int n = b * 1024 + t;
    int c = (n < NNODE) ? g_cnt[n] : 0;

    sh[t] = c;
    __syncthreads();
    for (int off = 1; off < 1024; off <<= 1) {
        int v = (t >= off) ? sh[t - off] : 0;
        __syncthreads();
        sh[t] += v;
        __syncthreads();
    }
    int incl = sh[t];

    if (t == 1023) {
        *(volatile int*)&g_aggval[b] = incl;
        __threadfence();
        *(volatile int*)&g_aggflag[b] = 1;
    }

    int part = 0;
    if (t < b) {
        while (*(volatile int*)&g_aggflag[t] == 0) { }
        part = *(volatile int*)&g_aggval[t];
    }
    sh2[t] = part;
    __syncthreads();
    for (int off = 512; off > 0; off >>= 1) {
        if (t < off) sh2[t] += sh2[t + off];
        __syncthreads();
    }
    int blockOff = sh2[0];

    if (n < NNODE) {
        int p = blockOff + incl - c;
        g_rowptr[n] = p;
        g_cursor[n] = p;
        float dg = g_wdeg[n];
        g_dinv[n] = (dg > 0.f) ? rsqrtf(dg) : 0.f;
    }
    if (b == 0 && t == 0) g_rowptr[NNODE] = NEDGE;
}

// bucket edges by destination; store {src, edge_w * dinv[src]}; 2 edges/thread
__global__ void __launch_bounds__(256) scatter_kernel(const int* __restrict__ eidx) {
    int e = (blockIdx.x * blockDim.x + threadIdx.x) * 2;
    if (e >= NEDGE) return;
    int2   r2 = __ldg(reinterpret_cast<const int2*>(eidx + e));
    int2   c2 = __ldg(reinterpret_cast<const int2*>(eidx + NEDGE + e));
    float2 w2 = __ldg(reinterpret_cast<const float2*>(g_edge_w + e));

    float wa = w2.x * __ldg(&g_dinv[r2.x]);
    int pa = atomicAdd(&g_cursor[c2.x], 1);
    g_edge[pa] = make_int2(r2.x, __float_as_int(wa));

    float wb = w2.y * __ldg(&g_dinv[r2.y]);
    int pb = atomicAdd(&g_cursor[c2.y], 1);
    g_edge[pb] = make_int2(r2.y, __float_as_int(wb));
}

// Shared gather body: warp = 1 node. Meta for up to 32 edges loaded in ONE
// coalesced int2 load, distributed to 4 edge-slots via shuffle. Inner loop
// iterations are memory-independent -> row loads issue concurrently.
// After the slot reduction, ALL lanes hold the node's sums for their sub's 8 dims.
__device__ __forceinline__ void gather_body(const uint4* __restrict__ xin,
                                            int node, int lane, float a[8]) {
    int slot = lane >> 3;     // 0..3 : edge within group of 4
    int sub  = lane & 7;      // 0..7 : 16B chunk of the 128B row

    int rp  = __ldg(&g_rowptr[node + (lane & 1)]);   // lane parity trick: 0->beg,1->end
    int beg = __shfl_sync(0xffffffffu, rp, 0);
    int end = __shfl_sync(0xffffffffu, rp, 1);
    int deg = end - beg;

    #pragma unroll
    for (int i = 0; i < 8; i++) a[i] = 0.f;

    for (int base = 0; base < deg; base += 32) {
        int idx = base + lane;
        int2 m = (idx < deg) ? __ldg(&g_edge[beg + idx]) : make_int2(0, 0);
        int nloc = min(deg - base, 32);
        for (int g = 0; g < nloc; g += 4) {
            int which = g + slot;                           // <= 31 always
            int  src = __shfl_sync(0xffffffffu, m.x, which);
            float w  = __int_as_float(__shfl_sync(0xffffffffu, m.y, which));
            uint4 v = __ldg(xin + (size_t)src * 8 + sub);
            float2 f0 = __half22float2(*reinterpret_cast<__half2*>(&v.x));
            float2 f1 = __half22float2(*reinterpret_cast<__half2*>(&v.y));
            float2 f2 = __half22float2(*reinterpret_cast<__half2*>(&v.z));
            float2 f3 = __half22float2(*reinterpret_cast<__half2*>(&v.w));
            a[0] = fmaf(w, f0.x, a[0]); a[1] = fmaf(w, f0.y, a[1]);
            a[2] = fmaf(w, f1.x, a[2]); a[3] = fmaf(w, f1.y, a[3]);
            a[4] = fmaf(w, f2.x, a[4]); a[5] = fmaf(w, f2.y, a[5]);
            a[6] = fmaf(w, f3.x, a[6]); a[7] = fmaf(w, f3.y, a[7]);
        }
    }
    // reduce across the 4 edge slots; every lane ends with full sums
    #pragma unroll
    for (int i = 0; i < 8; i++) {
        a[i] += __shfl_xor_sync(0xffffffffu, a[i], 8);
        a[i] += __shfl_xor_sync(0xffffffffu, a[i], 16);
    }
}

// layers 0,1: x[l+1][n] = dinv[n] * sum  (fp16 out)
__global__ void __launch_bounds__(256) gather_kernel(int layer) {
    const uint4* __restrict__ xin  = reinterpret_cast<const uint4*>(g_xptr[layer]);
    uint4*       __restrict__ xout = reinterpret_cast<uint4*>(g_xptr[layer + 1]);

    int warp = (blockIdx.x * blockDim.x + threadIdx.x) >> 5;
    int lane = threadIdx.x & 31;
    if (warp >= NNODE) return;

    float a[8];
    gather_body(xin, warp, lane, a);

    if ((lane >> 3) == 0) {
        int sub = lane & 7;
        float dv = __ldg(&g_dinv[warp]);
        __half2 h0 = __floats2half2_rn(a[0] * dv, a[1] * dv);
        __half2 h1 = __floats2half2_rn(a[2] * dv, a[3] * dv);
        __half2 h2 = __floats2half2_rn(a[4] * dv, a[5] * dv);
        __half2 h3 = __floats2half2_rn(a[6] * dv, a[7] * dv);
        uint4 o;
        o.x = *reinterpret_cast<unsigned int*>(&h0);
        o.y = *reinterpret_cast<unsigned int*>(&h1);
        o.z = *reinterpret_cast<unsigned int*>(&h2);
        o.w = *reinterpret_cast<unsigned int*>(&h3);
        xout[(size_t)warp * 8 + sub] = o;
    }
}

// layer 2 fused with final: out = l2norm((x0+x1+x2+x3)/4); also re-zeros
// g_wdeg/g_cnt for the next call; trailing align_loss scalar = 0.
__global__ void __launch_bounds__(256) gatherfinal_kernel(float* __restrict__ out) {
    int gt = blockIdx.x * blockDim.x + threadIdx.x;
    if (gt < NNODE) { g_wdeg[gt] = 0.f; g_cnt[gt] = 0; }
    if (gt == 0) out[(size_t)NNODE * DIM] = 0.f;

    int warp = gt >> 5;
    int lane = threadIdx.x & 31;
    if (warp >= NNODE) return;
    int sub = lane & 7;

    float a[8];
    gather_body(reinterpret_cast<const uint4*>(g_x2), warp, lane, a);

    float dv = __ldg(&g_dinv[warp]);
    float s[8];
    #pragma unroll
    for (int i = 0; i < 8; i++) s[i] = a[i] * dv;     // x3 in fp32 (pre-rounding)

    // add x0 + x1 + x2 (each row L1/L2-hot, same addr across the 4 slots)
    #pragma unroll
    for (int l = 0; l < 3; l++) {
        uint4 v = __ldg(reinterpret_cast<const uint4*>(g_xptr[l]) + (size_t)warp * 8 + sub);
        float2 f0 = __half22float2(*reinterpret_cast<__half2*>(&v.x));
        float2 f1 = __half22float2(*reinterpret_cast<__half2*>(&v.y));
        float2 f2 = __half22float2(*reinterpret_cast<__half2*>(&v.z));
        float2 f3 = __half22float2(*reinterpret_cast<__half2*>(&v.w));
        s[0] += f0.x; s[1] += f0.y; s[2] += f1.x; s[3] += f1.y;
        s[4] += f2.x; s[5] += f2.y; s[6] += f3.x; s[7] += f3.y;
    }
    float ss = 0.f;
    #pragma unroll
    for (int i = 0; i < 8; i++) { s[i] *= 0.25f; ss = fmaf(s[i], s[i], ss); }
    // reduce across the 8 sub groups (xor 1,2,4 stays within sub bits)
    #pragma unroll
    for (int o = 4; o > 0; o >>= 1) ss += __shfl_xor_sync(0xffffffffu, ss, o);
    float inv = 1.f / fmaxf(sqrtf(ss), 1e-12f);

    if ((lane >> 3) == 0) {
        float4* op = reinterpret_cast<float4*>(out);
        op[(size_t)warp * 16 + 2 * sub]     = make_float4(s[0] * inv, s[1] * inv, s[2] * inv, s[3] * inv);
        op[(size_t)warp * 16 + 2 * sub + 1] = make_float4(s[4] * inv, s[5] * inv, s[6] * inv, s[7] * inv);
    }
}

// ---------------- launcher ----------------
extern "C" void kernel_launch(void* const* d_in, const int* in_sizes, int n_in,
                              void* d_out, int out_size) {
    const float* uemb  = (const float*)d_in[0];
    const float* audio = (const float*)d_in[1];
    const float* art   = (const float*)d_in[2];
    const float* alb   = (const float*)d_in[3];
    const float* w1    = (const float*)d_in[4];
    const float* b1    = (const float*)d_in[5];
    const float* w2    = (const float*)d_in[6];
    const float* b2    = (const float*)d_in[7];
    const float* ef    = (const float*)d_in[8];
    const int*   eidx  = (const int*)  d_in[9];
    const int*   aid   = (const int*)  d_in[10];
    const int*   bid   = (const int*)  d_in[11];
    float* out = (float*)d_out;

    const int edge2Blocks = (NEDGE / 2 + 255) / 256;
    const int warpBlocks  = (NNODE * 32 + 255) / 256;   // one warp per node

    initmlp_kernel    <<<VECB + EDGEB, 256>>>(uemb, audio, art, alb, aid, bid,
                                              ef, w1, b1, w2, b2, eidx);
    scan_kernel       <<<SCANB, 1024>>>();
    scatter_kernel    <<<edge2Blocks, 256>>>(eidx);
    gather_kernel     <<<warpBlocks, 256>>>(0);   // x0 -> x1  (ncu launch index 3)
    gather_kernel     <<<warpBlocks, 256>>>(1);   // x1 -> x2
    gatherfinal_kernel<<<warpBlocks, 256>>>(out); // x2 -> out (fused final)
}

// round 8
// speedup vs baseline: 1.1555x; 1.0370x over previous
#include <cuda_runtime.h>
#include <cuda_fp16.h>
#include <math.h>
#include <stdint.h>

// ---------------- problem constants ----------------
static constexpr int NUSERS = 100000;
static constexpr int NITEMS = 50000;
static constexpr int NNODE  = 150000;       // NUSERS + NITEMS
static constexpr int NEDGE  = 1200000;      // 2 * 600000
static constexpr int DIM    = 64;
static constexpr int SCANB  = (NNODE + 1023) / 1024;   // 147 scan blocks

// ---------------- device scratch (static; no runtime alloc) ----------------
__device__ float  g_edge_w[NEDGE];
__device__ int2   g_edge[NEDGE];            // {src, __float_as_int(edge_w * dinv[src])}
__device__ float  g_wdeg[NNODE];
__device__ float  g_dinv[NNODE];
__device__ int    g_cnt[NNODE];
__device__ int    g_rowptr[NNODE + 1];
__device__ int    g_cursor[NNODE];
__device__ int    g_bsum[SCANB];
__device__ __half g_x0[(size_t)NNODE * DIM];
__device__ __half g_x1[(size_t)NNODE * DIM];
__device__ __half g_x2[(size_t)NNODE * DIM];
__device__ __half* const g_xptr[3] = {g_x0, g_x1, g_x2};

// ---------------- packed f32x2 helpers ----------------
__device__ __forceinline__ unsigned long long h2f2(unsigned int h) {
    float2 f = __half22float2(*reinterpret_cast<const __half2*>(&h));
    unsigned long long r;
    asm("mov.b64 %0, {%1, %2};" : "=l"(r) : "f"(f.x), "f"(f.y));
    return r;
}
__device__ __forceinline__ void ffma2(unsigned long long& d,
                                      unsigned long long a, unsigned long long b) {
    asm("fma.rn.f32x2 %0, %1, %2, %0;" : "+l"(d) : "l"(a), "l"(b));
}

// ---------------- kernels ----------------

// x0 = [ l2norm(user_emb) ; l2norm(0.3*audio + 0.44*(artist+album)) ]  (fp16)
// 16 lanes per node, float4 per lane. Also zeroes g_wdeg / g_cnt (fused).
__global__ void __launch_bounds__(256) init_kernel(const float* __restrict__ uemb,
                            const float* __restrict__ audio,
                            const float* __restrict__ art,
                            const float* __restrict__ alb,
                            const int*   __restrict__ aid,
                            const int*   __restrict__ bid) {
    int t = blockIdx.x * blockDim.x + threadIdx.x;
    if (t < NNODE) { g_wdeg[t] = 0.f; g_cnt[t] = 0; }

    int node = t >> 4;
    int sub  = t & 15;
    if (node >= NNODE) return;

    float4 v;
    if (node < NUSERS) {
        v = __ldg(reinterpret_cast<const float4*>(uemb) + (size_t)node * 16 + sub);
    } else {
        int i = node - NUSERS;
        int a = __ldg(&aid[i]);
        int b = __ldg(&bid[i]);
        float4 pa = __ldg(reinterpret_cast<const float4*>(audio) + (size_t)i * 16 + sub);
        float4 pr = __ldg(reinterpret_cast<const float4*>(art)   + (size_t)a * 16 + sub);
        float4 pl = __ldg(reinterpret_cast<const float4*>(alb)   + (size_t)b * 16 + sub);
        v.x = pa.x * 0.3f + (pr.x + pl.x) * 0.44f;
        v.y = pa.y * 0.3f + (pr.y + pl.y) * 0.44f;
        v.z = pa.z * 0.3f + (pr.z + pl.z) * 0.44f;
        v.w = pa.w * 0.3f + (pr.w + pl.w) * 0.44f;
    }
    float ss = v.x * v.x + v.y * v.y + v.z * v.z + v.w * v.w;
    #pragma unroll
    for (int o = 8; o > 0; o >>= 1) ss += __shfl_xor_sync(0xffffffffu, ss, o);
    float inv = 1.f / fmaxf(sqrtf(ss), 1e-12f);

    __half2 h0 = __floats2half2_rn(v.x * inv, v.y * inv);
    __half2 h1 = __floats2half2_rn(v.z * inv, v.w * inv);
    uint2 hv;
    hv.x = *reinterpret_cast<unsigned int*>(&h0);
    hv.y = *reinterpret_cast<unsigned int*>(&h1);
    reinterpret_cast<uint2*>(g_x0)[(size_t)node * 16 + sub] = hv;
}

// edge gate MLP: sigmoid(relu(f @ W1 + b1) @ w2 + b2); histogram weighted degree + count
__global__ void mlp_kernel(const float* __restrict__ ef,
                           const float* __restrict__ w1,
                           const float* __restrict__ b1,
                           const float* __restrict__ w2,
                           const float* __restrict__ b2,
                           const int*   __restrict__ eidx) {
    __shared__ float sW1[8 * 32];
    __shared__ float sB1[32];
    __shared__ float sW2[32];
    __shared__ float sB2;
    int t = threadIdx.x;
    if (t < 256) sW1[t] = w1[t];
    if (t < 32)  { sB1[t] = b1[t]; sW2[t] = w2[t]; }
    if (t == 0)  sB2 = b2[0];
    __syncthreads();

    int e = blockIdx.x * blockDim.x + t;
    if (e >= NEDGE) return;

    const float4* fp = reinterpret_cast<const float4*>(ef + (size_t)e * 8);
    float4 fa = fp[0];
    float4 fb = fp[1];
    float f[8] = {fa.x, fa.y, fa.z, fa.w, fb.x, fb.y, fb.z, fb.w};

    float out = sB2;
    #pragma unroll
    for (int j = 0; j < 32; j++) {
        float h = sB1[j];
        #pragma unroll
        for (int i = 0; i < 8; i++) h = fmaf(f[i], sW1[i * 32 + j], h);
        h = fmaxf(h, 0.f);
        out = fmaf(h, sW2[j], out);
    }
    float w = 1.f / (1.f + expf(-out));

    g_edge_w[e] = w;
    int c = eidx[NEDGE + e];
    atomicAdd(&g_wdeg[c], w);
    atomicAdd(&g_cnt[c], 1);
}

// scan phase 1: per-block sums of g_cnt
__global__ void __launch_bounds__(1024) scan1_kernel() {
    __shared__ int sh[1024];
    int n = blockIdx.x * 1024 + threadIdx.x;
    int s = (n < NNODE) ? g_cnt[n] : 0;
    sh[threadIdx.x] = s;
    __syncthreads();
    for (int off = 512; off > 0; off >>= 1) {
        if (threadIdx.x < off) sh[threadIdx.x] += sh[threadIdx.x + off];
        __syncthreads();
    }
    if (threadIdx.x == 0) g_bsum[blockIdx.x] = sh[0];
}

// scan phase 2+3 fused: each block redundantly scans the 147 block sums,
// then does its local exclusive scan and writes rowptr/cursor/dinv.
__global__ void __launch_bounds__(1024) scan3_kernel() {
    __shared__ int sums[256];
    __shared__ int sh[1024];
    int t = threadIdx.x;
    if (t < 256) sums[t] = (t < SCANB) ? g_bsum[t] : 0;
    __syncthreads();
    for (int off = 1; off < 256; off <<= 1) {
        int v = (t < 256 && t >= off) ? sums[t - off] : 0;
        __syncthreads();
        if (t < 256) sums[t] += v;
        __syncthreads();
    }
    int blockOff = (blockIdx.x == 0) ? 0 : sums[blockIdx.x - 1];

    int n = blockIdx.x * 1024 + t;
    int c = (n < NNODE) ? g_cnt[n] : 0;
    sh[t] = c;
    __syncthreads();
    for (int off = 1; off < 1024; off <<= 1) {
        int v = (t >= off) ? sh[t - off] : 0;
        __syncthreads();
        sh[t] += v;
        __syncthreads();
    }
    if (n < NNODE) {
        int p = blockOff + sh[t] - c;   // global exclusive prefix
        g_rowptr[n] = p;
        g_cursor[n] = p;
        float dg = g_wdeg[n];
        g_dinv[n] = (dg > 0.f) ? rsqrtf(dg) : 0.f;
    }
    if (blockIdx.x == 0 && t == 0) g_rowptr[NNODE] = NEDGE;
}

// bucket edges by destination; store {src, edge_w * dinv[src]}; 2 edges/thread
__global__ void __launch_bounds__(256) scatter_kernel(const int* __restrict__ eidx) {
    int e = (blockIdx.x * blockDim.x + threadIdx.x) * 2;
    if (e >= NEDGE) return;
    int2   r2 = __ldg(reinterpret_cast<const int2*>(eidx + e));
    int2   c2 = __ldg(reinterpret_cast<const int2*>(eidx + NEDGE + e));
    float2 w2 = __ldg(reinterpret_cast<const float2*>(g_edge_w + e));

    float wa = w2.x * __ldg(&g_dinv[r2.x]);
    int pa = atomicAdd(&g_cursor[c2.x], 1);
    g_edge[pa] = make_int2(r2.x, __float_as_int(wa));

    float wb = w2.y * __ldg(&g_dinv[r2.y]);
    int pb = atomicAdd(&g_cursor[c2.y], 1);
    g_edge[pb] = make_int2(r2.y, __float_as_int(wb));
}

// Shared gather body: warp = 1 node. Meta for up to 32 edges loaded in ONE
// coalesced int2 load, distributed via shuffle. 8 edges per inner iteration
// (2 per lane, in 4 slot-groups), packed f32x2 FMA accumulation.
// After reduction ALL lanes hold the node's sums for their sub's 8 dims.
__device__ __forceinline__ void gather_body(const uint4* __restrict__ xin,
                                            int node, int lane, float a[8]) {
    int slot = lane >> 3;     // 0..3
    int sub  = lane & 7;      // 0..7 : 16B chunk of the 128B row

    int rp  = __ldg(&g_rowptr[node + (lane & 1)]);
    int beg = __shfl_sync(0xffffffffu, rp, 0);
    int end = __shfl_sync(0xffffffffu, rp, 1);
    int deg = end - beg;

    unsigned long long acc[4] = {0ull, 0ull, 0ull, 0ull};

    for (int base = 0; base < deg; base += 32) {
        int idx = base + lane;
        int2 m = (idx < deg) ? __ldg(&g_edge[beg + idx]) : make_int2(0, 0);
        int nloc = min(deg - base, 32);
        for (int g = 0; g < nloc; g += 8) {
            int s0  = __shfl_sync(0xffffffffu, m.x, g + slot);
            int w0i = __shfl_sync(0xffffffffu, m.y, g + slot);
            int s1  = __shfl_sync(0xffffffffu, m.x, g + 4 + slot);
            int w1i = __shfl_sync(0xffffffffu, m.y, g + 4 + slot);
            uint4 v0 = __ldg(xin + (size_t)s0 * 8 + sub);
            uint4 v1 = __ldg(xin + (size_t)s1 * 8 + sub);
            float w0 = __int_as_float(w0i);
            float w1 = __int_as_float(w1i);
            unsigned long long wp0, wp1;
            asm("mov.b64 %0, {%1, %1};" : "=l"(wp0) : "f"(w0));
            asm("mov.b64 %0, {%1, %1};" : "=l"(wp1) : "f"(w1));
            ffma2(acc[0], h2f2(v0.x), wp0);
            ffma2(acc[1], h2f2(v0.y), wp0);
            ffma2(acc[2], h2f2(v0.z), wp0);
            ffma2(acc[3], h2f2(v0.w), wp0);
            ffma2(acc[0], h2f2(v1.x), wp1);
            ffma2(acc[1], h2f2(v1.y), wp1);
            ffma2(acc[2], h2f2(v1.z), wp1);
            ffma2(acc[3], h2f2(v1.w), wp1);
        }
    }
    #pragma unroll
    for (int i = 0; i < 4; i++)
        asm("mov.b64 {%0, %1}, %2;" : "=f"(a[2 * i]), "=f"(a[2 * i + 1]) : "l"(acc[i]));
    // reduce across the 4 edge slots; every lane ends with full sums
    #pragma unroll
    for (int i = 0; i < 8; i++) {
        a[i] += __shfl_xor_sync(0xffffffffu, a[i], 8);
        a[i] += __shfl_xor_sync(0xffffffffu, a[i], 16);
    }
}

// layers 0,1: x[l+1][n] = dinv[n] * sum  (fp16 out)
__global__ void __launch_bounds__(256) gather_kernel(int layer) {
    const uint4* __restrict__ xin  = reinterpret_cast<const uint4*>(g_xptr[layer]);
    uint4*       __restrict__ xout = reinterpret_cast<uint4*>(g_xptr[layer + 1]);

    int warp = (blockIdx.x * blockDim.x + threadIdx.x) >> 5;
    int lane = threadIdx.x & 31;
    if (warp >= NNODE) return;

    float a[8];
    gather_body(xin, warp, lane, a);

    if ((lane >> 3) == 0) {
        int sub = lane & 7;
        float dv = __ldg(&g_dinv[warp]);
        __half2 h0 = __floats2half2_rn(a[0] * dv, a[1] * dv);
        __half2 h1 = __floats2half2_rn(a[2] * dv, a[3] * dv);
        __half2 h2 = __floats2half2_rn(a[4] * dv, a[5] * dv);
        __half2 h3 = __floats2half2_rn(a[6] * dv, a[7] * dv);
        uint4 o;
        o.x = *reinterpret_cast<unsigned int*>(&h0);
        o.y = *reinterpret_cast<unsigned int*>(&h1);
        o.z = *reinterpret_cast<unsigned int*>(&h2);
        o.w = *reinterpret_cast<unsigned int*>(&h3);
        xout[(size_t)warp * 8 + sub] = o;
    }
}

// layer 2 fused with final: out = l2norm((x0+x1+x2+x3)/4); x3 stays in fp32.
__global__ void __launch_bounds__(256) gatherfinal_kernel(float* __restrict__ out) {
    int gt = blockIdx.x * blockDim.x + threadIdx.x;
    if (gt == 0) out[(size_t)NNODE * DIM] = 0.f;   // align_loss scalar

    int warp = gt >> 5;
    int lane = threadIdx.x & 31;
    if (warp >= NNODE) return;
    int sub = lane & 7;

    float a[8];
    gather_body(reinterpret_cast<const uint4*>(g_x2), warp, lane, a);

    float dv = __ldg(&g_dinv[warp]);
    float s[8];
    #pragma unroll
    for (int i = 0; i < 8; i++) s[i] = a[i] * dv;

    #pragma unroll
    for (int l = 0; l < 3; l++) {
        uint4 v = __ldg(reinterpret_cast<const uint4*>(g_xptr[l]) + (size_t)warp * 8 + sub);
        float2 f0 = __half22float2(*reinterpret_cast<__half2*>(&v.x));
        float2 f1 = __half22float2(*reinterpret_cast<__half2*>(&v.y));
        float2 f2 = __half22float2(*reinterpret_cast<__half2*>(&v.z));
        float2 f3 = __half22float2(*reinterpret_cast<__half2*>(&v.w));
        s[0] += f0.x; s[1] += f0.y; s[2] += f1.x; s[3] += f1.y;
        s[4] += f2.x; s[5] += f2.y; s[6] += f3.x; s[7] += f3.y;
    }
    float ss = 0.f;
    #pragma unroll
    for (int i = 0; i < 8; i++) { s[i] *= 0.25f; ss = fmaf(s[i], s[i], ss); }
    #pragma unroll
    for (int o = 4; o > 0; o >>= 1) ss += __shfl_xor_sync(0xffffffffu, ss, o);
    float inv = 1.f / fmaxf(sqrtf(ss), 1e-12f);

    if ((lane >> 3) == 0) {
        float4* op = reinterpret_cast<float4*>(out);
        op[(size_t)warp * 16 + 2 * sub]     = make_float4(s[0] * inv, s[1] * inv, s[2] * inv, s[3] * inv);
        op[(size_t)warp * 16 + 2 * sub + 1] = make_float4(s[4] * inv, s[5] * inv, s[6] * inv, s[7] * inv);
    }
}

// ---------------- launcher ----------------
extern "C" void kernel_launch(void* const* d_in, const int* in_sizes, int n_in,
                              void* d_out, int out_size) {
    const float* uemb  = (const float*)d_in[0];
    const float* audio = (const float*)d_in[1];
    const float* art   = (const float*)d_in[2];
    const float* alb   = (const float*)d_in[3];
    const float* w1    = (const float*)d_in[4];
    const float* b1    = (const float*)d_in[5];
    const float* w2    = (const float*)d_in[6];
    const float* b2    = (const float*)d_in[7];
    const float* ef    = (const float*)d_in[8];
    const int*   eidx  = (const int*)  d_in[9];
    const int*   aid   = (const int*)  d_in[10];
    const int*   bid   = (const int*)  d_in[11];
    float* out = (float*)d_out;

    const int edgeBlocks  = (NEDGE + 255) / 256;
    const int edge2Blocks = (NEDGE / 2 + 255) / 256;
    const int warpBlocks  = (NNODE * 32 + 255) / 256;   // one warp per node
    const int vecBlocks   = (NNODE * 16 + 255) / 256;   // 16 lanes per node

    init_kernel       <<<vecBlocks, 256>>>(uemb, audio, art, alb, aid, bid);
    mlp_kernel        <<<edgeBlocks, 256>>>(ef, w1, b1, w2, b2, eidx);
    scan1_kernel      <<<SCANB, 1024>>>();
    scan3_kernel      <<<SCANB, 1024>>>();
    scatter_kernel    <<<edge2Blocks, 256>>>(eidx);
    gather_kernel     <<<warpBlocks, 256>>>(0);   // x0 -> x1
    gather_kernel     <<<warpBlocks, 256>>>(1);   // x1 -> x2
    gatherfinal_kernel<<<warpBlocks, 256>>>(out); // x2 -> out (fused final)
}

// round 9
// speedup vs baseline: 1.1785x; 1.0199x over previous
#include <cuda_runtime.h>
#include <cuda_fp16.h>
#include <math.h>
#include <stdint.h>

// ---------------- problem constants ----------------
static constexpr int NUSERS = 100000;
static constexpr int NITEMS = 50000;
static constexpr int NNODE  = 150000;       // NUSERS + NITEMS
static constexpr int NEDGE  = 1200000;      // 2 * 600000
static constexpr int DIM    = 64;
static constexpr int SCANB  = (NNODE + 1023) / 1024;     // 147 scan blocks
static constexpr int EDGE2B = (NEDGE / 2 + 255) / 256;   // scatter blocks
static constexpr int VECB   = (NNODE * 16 + 255) / 256;  // init blocks

// ---------------- device scratch (static; no runtime alloc) ----------------
// Invariant: g_wdeg/g_cnt are ZERO at kernel_launch entry (static init covers
// the first call; gatherfinal_kernel re-zeros them at the end of every call).
__device__ float  g_edge_w[NEDGE];
__device__ int2   g_edge[NEDGE];            // {src, __float_as_int(edge_w * dinv[src])}
__device__ float  g_wdeg[NNODE];
__device__ float  g_dinv[NNODE];
__device__ int    g_cnt[NNODE];
__device__ int    g_rowptr[NNODE + 1];
__device__ int    g_cursor[NNODE];
__device__ int    g_bsum[SCANB];
__device__ __half g_x0[(size_t)NNODE * DIM];
__device__ __half g_x1[(size_t)NNODE * DIM];
__device__ __half g_x2[(size_t)NNODE * DIM];
__device__ __half* const g_xptr[3] = {g_x0, g_x1, g_x2};

// ---------------- kernels ----------------

// edge gate MLP: sigmoid(relu(f @ W1 + b1) @ w2 + b2); histogram wdeg + cnt
__global__ void mlp_kernel(const float* __restrict__ ef,
                           const float* __restrict__ w1,
                           const float* __restrict__ b1,
                           const float* __restrict__ w2,
                           const float* __restrict__ b2,
                           const int*   __restrict__ eidx) {
    __shared__ float sW1[8 * 32];
    __shared__ float sB1[32];
    __shared__ float sW2[32];
    __shared__ float sB2;
    int t = threadIdx.x;
    if (t < 256) sW1[t] = w1[t];
    if (t < 32)  { sB1[t] = b1[t]; sW2[t] = w2[t]; }
    if (t == 0)  sB2 = b2[0];
    __syncthreads();

    int e = blockIdx.x * blockDim.x + t;
    if (e >= NEDGE) return;

    const float4* fp = reinterpret_cast<const float4*>(ef + (size_t)e * 8);
    float4 fa = fp[0];
    float4 fb = fp[1];
    float f[8] = {fa.x, fa.y, fa.z, fa.w, fb.x, fb.y, fb.z, fb.w};

    float out = sB2;
    #pragma unroll
    for (int j = 0; j < 32; j++) {
        float h = sB1[j];
        #pragma unroll
        for (int i = 0; i < 8; i++) h = fmaf(f[i], sW1[i * 32 + j], h);
        h = fmaxf(h, 0.f);
        out = fmaf(h, sW2[j], out);
    }
    float w = 1.f / (1.f + expf(-out));

    g_edge_w[e] = w;
    int c = eidx[NEDGE + e];
    atomicAdd(&g_wdeg[c], w);
    atomicAdd(&g_cnt[c], 1);
}

// scan phase 1: per-block sums of g_cnt
__global__ void __launch_bounds__(1024) scan1_kernel() {
    __shared__ int sh[1024];
    int n = blockIdx.x * 1024 + threadIdx.x;
    int s = (n < NNODE) ? g_cnt[n] : 0;
    sh[threadIdx.x] = s;
    __syncthreads();
    for (int off = 512; off > 0; off >>= 1) {
        if (threadIdx.x < off) sh[threadIdx.x] += sh[threadIdx.x + off];
        __syncthreads();
    }
    if (threadIdx.x == 0) g_bsum[blockIdx.x] = sh[0];
}

// scan phase 2+3: each block redundantly scans the 147 block sums, then does
// its local exclusive scan and writes rowptr/cursor/dinv.
__global__ void __launch_bounds__(1024) scan3_kernel() {
    __shared__ int sums[256];
    __shared__ int sh[1024];
    int t = threadIdx.x;
    if (t < 256) sums[t] = (t < SCANB) ? g_bsum[t] : 0;
    __syncthreads();
    for (int off = 1; off < 256; off <<= 1) {
        int v = (t < 256 && t >= off) ? sums[t - off] : 0;
        __syncthreads();
        if (t < 256) sums[t] += v;
        __syncthreads();
    }
    int blockOff = (blockIdx.x == 0) ? 0 : sums[blockIdx.x - 1];

    int n = blockIdx.x * 1024 + t;
    int c = (n < NNODE) ? g_cnt[n] : 0;
    sh[t] = c;
    __syncthreads();
    for (int off = 1; off < 1024; off <<= 1) {
        int v = (t >= off) ? sh[t - off] : 0;
        __syncthreads();
        sh[t] += v;
        __syncthreads();
    }
    if (n < NNODE) {
        int p = blockOff + sh[t] - c;
        g_rowptr[n] = p;
        g_cursor[n] = p;
        float dg = g_wdeg[n];
        g_dinv[n] = (dg > 0.f) ? rsqrtf(dg) : 0.f;
    }
    if (blockIdx.x == 0 && t == 0) g_rowptr[NNODE] = NEDGE;
}

// fused scatter + init:
//   blocks [0, EDGE2B): bucket edges by destination {src, edge_w*dinv[src]}
//   blocks [EDGE2B, EDGE2B+VECB): x0 = l2norm(...) node init (independent work)
__global__ void __launch_bounds__(256) scatterinit_kernel(
        const int*   __restrict__ eidx,
        const float* __restrict__ uemb,  const float* __restrict__ audio,
        const float* __restrict__ art,   const float* __restrict__ alb,
        const int*   __restrict__ aid,   const int*   __restrict__ bid) {
    if (blockIdx.x < EDGE2B) {
        int e = (blockIdx.x * 256 + threadIdx.x) * 2;
        if (e >= NEDGE) return;
        int2   r2 = __ldg(reinterpret_cast<const int2*>(eidx + e));
        int2   c2 = __ldg(reinterpret_cast<const int2*>(eidx + NEDGE + e));
        float2 w2 = __ldg(reinterpret_cast<const float2*>(g_edge_w + e));

        float wa = w2.x * __ldg(&g_dinv[r2.x]);
        int pa = atomicAdd(&g_cursor[c2.x], 1);
        g_edge[pa] = make_int2(r2.x, __float_as_int(wa));

        float wb = w2.y * __ldg(&g_dinv[r2.y]);
        int pb = atomicAdd(&g_cursor[c2.y], 1);
        g_edge[pb] = make_int2(r2.y, __float_as_int(wb));
    } else {
        int t = (blockIdx.x - EDGE2B) * 256 + threadIdx.x;
        int node = t >> 4;
        int sub  = t & 15;
        if (node >= NNODE) return;

        float4 v;
        if (node < NUSERS) {
            v = __ldg(reinterpret_cast<const float4*>(uemb) + (size_t)node * 16 + sub);
        } else {
            int i = node - NUSERS;
            int a = __ldg(&aid[i]);
            int b = __ldg(&bid[i]);
            float4 pa = __ldg(reinterpret_cast<const float4*>(audio) + (size_t)i * 16 + sub);
            float4 pr = __ldg(reinterpret_cast<const float4*>(art)   + (size_t)a * 16 + sub);
            float4 pl = __ldg(reinterpret_cast<const float4*>(alb)   + (size_t)b * 16 + sub);
            v.x = pa.x * 0.3f + (pr.x + pl.x) * 0.44f;
            v.y = pa.y * 0.3f + (pr.y + pl.y) * 0.44f;
            v.z = pa.z * 0.3f + (pr.z + pl.z) * 0.44f;
            v.w = pa.w * 0.3f + (pr.w + pl.w) * 0.44f;
        }
        float ss = v.x * v.x + v.y * v.y + v.z * v.z + v.w * v.w;
        #pragma unroll
        for (int o = 8; o > 0; o >>= 1) ss += __shfl_xor_sync(0xffffffffu, ss, o);
        float inv = 1.f / fmaxf(sqrtf(ss), 1e-12f);

        __half2 h0 = __floats2half2_rn(v.x * inv, v.y * inv);
        __half2 h1 = __floats2half2_rn(v.z * inv, v.w * inv);
        uint2 hv;
        hv.x = *reinterpret_cast<unsigned int*>(&h0);
        hv.y = *reinterpret_cast<unsigned int*>(&h1);
        reinterpret_cast<uint2*>(g_x0)[(size_t)node * 16 + sub] = hv;
    }
}

// ---- gather body: warp = 1 node, lane owns dims {2*lane, 2*lane+1} ----
// Edge meta for up to 32 edges staged in ONE coalesced int2 load; each edge is
// ONE warp-wide 128B row load (4B/lane). 8 independent loads in flight per
// group; padded edges (staged as {0,0}) contribute w=0. No cross-lane
// reduction needed for the accumulate.
__device__ __forceinline__ float2 gather_body(const unsigned* __restrict__ xin,
                                              int node, int lane) {
    int rp  = __ldg(&g_rowptr[node + (lane & 1)]);
    int beg = __shfl_sync(0xffffffffu, rp, 0);
    int end = __shfl_sync(0xffffffffu, rp, 1);
    int deg = end - beg;

    float a0 = 0.f, a1 = 0.f;
    for (int base = 0; base < deg; base += 32) {
        int idx = base + lane;
        int2 m = (idx < deg) ? __ldg(&g_edge[beg + idx]) : make_int2(0, 0);
        int nr = (min(deg - base, 32) + 7) & ~7;   // round up to group of 8
        for (int g = 0; g < nr; g += 8) {
            unsigned v[8];
            float    w[8];
            #pragma unroll
            for (int k = 0; k < 8; k++) {
                int src = __shfl_sync(0xffffffffu, m.x, g + k);
                w[k] = __int_as_float(__shfl_sync(0xffffffffu, m.y, g + k));
                v[k] = __ldg(xin + (size_t)src * 32 + lane);
            }
            #pragma unroll
            for (int k = 0; k < 8; k++) {
                float2 f = __half22float2(*reinterpret_cast<__half2*>(&v[k]));
                a0 = fmaf(w[k], f.x, a0);
                a1 = fmaf(w[k], f.y, a1);
            }
        }
    }
    return make_float2(a0, a1);
}

// layers 0,1: x[l+1][n] = dinv[n] * sum  (fp16 out, fully coalesced store)
__global__ void __launch_bounds__(256) gather_kernel(int layer) {
    const unsigned* __restrict__ xin  = reinterpret_cast<const unsigned*>(g_xptr[layer]);
    unsigned*       __restrict__ xout = reinterpret_cast<unsigned*>(g_xptr[layer + 1]);

    int warp = (blockIdx.x * blockDim.x + threadIdx.x) >> 5;
    int lane = threadIdx.x & 31;
    if (warp >= NNODE) return;

    float2 a = gather_body(xin, warp, lane);
    float dv = __ldg(&g_dinv[warp]);
    __half2 h = __floats2half2_rn(a.x * dv, a.y * dv);
    xout[(size_t)warp * 32 + lane] = *reinterpret_cast<unsigned*>(&h);
}

// layer 2 fused with final: out = l2norm((x0+x1+x2+x3)/4), x3 kept fp32.
// Also re-zeros g_wdeg/g_cnt for the next call; align_loss scalar = 0.
__global__ void __launch_bounds__(256) gatherfinal_kernel(float* __restrict__ out) {
    int gt = blockIdx.x * blockDim.x + threadIdx.x;
    if (gt < NNODE) { g_wdeg[gt] = 0.f; g_cnt[gt] = 0; }
    if (gt == 0) out[(size_t)NNODE * DIM] = 0.f;

    int warp = gt >> 5;
    int lane = threadIdx.x & 31;
    if (warp >= NNODE) return;

    float2 a = gather_body(reinterpret_cast<const unsigned*>(g_x2), warp, lane);
    float dv = __ldg(&g_dinv[warp]);
    float s0 = a.x * dv;
    float s1 = a.y * dv;

    #pragma unroll
    for (int l = 0; l < 3; l++) {
        unsigned v = __ldg(reinterpret_cast<const unsigned*>(g_xptr[l]) + (size_t)warp * 32 + lane);
        float2 f = __half22float2(*reinterpret_cast<__half2*>(&v));
        s0 += f.x;
        s1 += f.y;
    }
    s0 *= 0.25f;
    s1 *= 0.25f;
    float ss = fmaf(s0, s0, s1 * s1);
    #pragma unroll
    for (int o = 16; o > 0; o >>= 1) ss += __shfl_xor_sync(0xffffffffu, ss, o);
    float inv = 1.f / fmaxf(sqrtf(ss), 1e-12f);

    reinterpret_cast<float2*>(out)[(size_t)warp * 32 + lane] = make_float2(s0 * inv, s1 * inv);
}

// ---------------- launcher ----------------
extern "C" void kernel_launch(void* const* d_in, const int* in_sizes, int n_in,
                              void* d_out, int out_size) {
    const float* uemb  = (const float*)d_in[0];
    const float* audio = (const float*)d_in[1];
    const float* art   = (const float*)d_in[2];
    const float* alb   = (const float*)d_in[3];
    const float* w1    = (const float*)d_in[4];
    const float* b1    = (const float*)d_in[5];
    const float* w2    = (const float*)d_in[6];
    const float* b2    = (const float*)d_in[7];
    const float* ef    = (const float*)d_in[8];
    const int*   eidx  = (const int*)  d_in[9];
    const int*   aid   = (const int*)  d_in[10];
    const int*   bid   = (const int*)  d_in[11];
    float* out = (float*)d_out;

    const int edgeBlocks = (NEDGE + 255) / 256;
    const int warpBlocks = (NNODE * 32 + 255) / 256;   // one warp per node

    mlp_kernel        <<<edgeBlocks, 256>>>(ef, w1, b1, w2, b2, eidx);
    scan1_kernel      <<<SCANB, 1024>>>();
    scan3_kernel      <<<SCANB, 1024>>>();
    scatterinit_kernel<<<EDGE2B + VECB, 256>>>(eidx, uemb, audio, art, alb, aid, bid);
    gather_kernel     <<<warpBlocks, 256>>>(0);   // x0 -> x1
    gather_kernel     <<<warpBlocks, 256>>>(1);   // x1 -> x2
    gatherfinal_kernel<<<warpBlocks, 256>>>(out); // x2 -> out (fused final)
}